// round 1
// baseline (speedup 1.0000x reference)
#include <cuda_runtime.h>
#include <math.h>

// ---------------- problem constants ----------------
#define TT 4096
#define HH 2048
#define EE 32
#define II 1024
#define TOPK 8
#define NGROUP 8
#define GSIZE 4      // EE / NGROUP
#define TOPKG 4
#define SSI 2048     // shared expert intermediate
#define RSCALE 2.5f

// ---------------- scratch (device globals; no allocs allowed) ----------------
constexpr size_t GU_ELEMS  = (size_t)EE * TT * 2 * II;   // 268,435,456 (1 GB)
constexpr size_t H_ELEMS   = (size_t)EE * TT * II;       // 134,217,728 (512 MB)
constexpr size_t GUS_ELEMS = (size_t)TT * 2 * SSI;       // 16,777,216  (64 MB)
constexpr size_t HS_ELEMS  = (size_t)TT * SSI;           // 8,388,608   (32 MB)

__device__ float g_cw[(size_t)TT * EE];
__device__ int   g_tok[(size_t)EE * TT];
__device__ int   g_cnt[EE];
__device__ float g_gu [GU_ELEMS];
__device__ float g_h  [H_ELEMS];
__device__ float g_gus[GUS_ELEMS];
__device__ float g_hs [HS_ELEMS];

// ---------------- router: logits + grouped top-k + dense combine weights ----------------
__global__ void router_kernel(const float* __restrict__ hs,
                              const float* __restrict__ gw,
                              const float* __restrict__ bias) {
    int t    = blockIdx.x * blockDim.y + threadIdx.y;  // one warp per token
    int lane = threadIdx.x;                            // one lane per expert

    const float* hrow = hs + (size_t)t * HH;
    float acc = 0.f;
    for (int h = 0; h < HH; h += 4) {
        float4 hv = *(const float4*)(hrow + h);
        acc += hv.x * gw[(h + 0) * EE + lane];
        acc += hv.y * gw[(h + 1) * EE + lane];
        acc += hv.z * gw[(h + 2) * EE + lane];
        acc += hv.w * gw[(h + 3) * EE + lane];
    }
    float score = 1.f / (1.f + expf(-acc));   // sigmoid
    float sc    = score + bias[lane];         // biased score (selection only)

    __shared__ float s_score[8][32];
    __shared__ float s_sc[8][32];
    s_score[threadIdx.y][lane] = score;
    s_sc[threadIdx.y][lane]    = sc;
    __syncwarp();

    if (lane == 0) {
        float scv[EE], scoresv[EE];
        for (int e = 0; e < EE; e++) { scv[e] = s_sc[threadIdx.y][e]; scoresv[e] = s_score[threadIdx.y][e]; }

        // group scores = sum of top-2 within each group of 4
        float gs[NGROUP];
        for (int g = 0; g < NGROUP; g++) {
            float m1 = -INFINITY; int i1 = 0;
            for (int j = 0; j < GSIZE; j++) {
                float v = scv[g * GSIZE + j];
                if (v > m1) { m1 = v; i1 = j; }
            }
            float m2 = -INFINITY;
            for (int j = 0; j < GSIZE; j++) {
                if (j != i1) { float v = scv[g * GSIZE + j]; if (v > m2) m2 = v; }
            }
            gs[g] = m1 + m2;
        }
        // top-4 groups (strict >, first index wins on ties == jax)
        bool gsel[NGROUP];
        for (int g = 0; g < NGROUP; g++) gsel[g] = false;
        for (int it = 0; it < TOPKG; it++) {
            float best = -INFINITY; int bi = 0;
            for (int g = 0; g < NGROUP; g++)
                if (!gsel[g] && gs[g] > best) { best = gs[g]; bi = g; }
            gsel[bi] = true;
        }
        // masked top-8 experts
        float masked[EE];
        for (int e = 0; e < EE; e++) masked[e] = gsel[e / GSIZE] ? scv[e] : -INFINITY;
        int   ids[TOPK]; float wv[TOPK]; float wsum = 0.f;
        for (int k = 0; k < TOPK; k++) {
            float best = -INFINITY; int bi = 0;
            for (int e = 0; e < EE; e++)
                if (masked[e] > best) { best = masked[e]; bi = e; }
            masked[bi] = -INFINITY;
            ids[k] = bi; wv[k] = scoresv[bi]; wsum += wv[k];
        }
        float inv = 1.f / (wsum + 1e-20f);
        float row[EE];
        for (int e = 0; e < EE; e++) row[e] = 0.f;
        for (int k = 0; k < TOPK; k++) row[ids[k]] = wv[k] * inv;
        for (int e = 0; e < EE; e++) g_cw[(size_t)t * EE + e] = row[e];
    }
}

// ---------------- per-expert token compaction (warp ballot, deterministic order) ----------------
__global__ void gather_kernel() {
    int e = blockIdx.x;
    int lane = threadIdx.x;
    int cnt = 0;
    for (int base = 0; base < TT; base += 32) {
        int t = base + lane;
        bool sel = g_cw[(size_t)t * EE + e] > 0.f;
        unsigned m = __ballot_sync(0xffffffffu, sel);
        int pos = cnt + __popc(m & ((1u << lane) - 1u));
        if (sel) g_tok[(size_t)e * TT + pos] = t;
        cnt += __popc(m);
    }
    if (lane == 0) g_cnt[e] = cnt;
}

// ---------------- activations ----------------
__global__ void act_shared_kernel() {
    size_t idx = (size_t)blockIdx.x * blockDim.x + threadIdx.x;  // over TT*SSI
    int t = (int)(idx / SSI);
    int j = (int)(idx % SSI);
    float g = g_gus[(size_t)t * 2 * SSI + j];
    float u = g_gus[(size_t)t * 2 * SSI + SSI + j];
    g_hs[idx] = u * (g / (1.f + expf(-g)));
}

__global__ void act_exp_kernel() {
    int e = blockIdx.y;
    int slot = blockIdx.x;
    if (slot >= g_cnt[e]) return;
    size_t gbase = ((size_t)e * TT + slot) * (2 * II);
    size_t hbase = ((size_t)e * TT + slot) * II;
    for (int j = threadIdx.x; j < II; j += blockDim.x) {
        float g = g_gu[gbase + j];
        float u = g_gu[gbase + II + j];
        g_h[hbase + j] = u * (g / (1.f + expf(-g)));
    }
}

// ---------------- unified tiled SGEMM ----------------
// GA: gather A rows through per-expert token list (A = hidden_states)
// SC: scatter C rows through token list with weight*scale atomicAdd
#define BMT 128
#define BNT 128
#define BKT 16

template<bool GA, bool SC>
__global__ __launch_bounds__(256, 2)
void sgemm_kernel(const float* __restrict__ A, size_t strideAe, int lda,
                  const float* __restrict__ B, size_t strideBe, int ldb,
                  float* __restrict__ C, size_t strideCe, int ldc,
                  int Mdir, const int* __restrict__ cntp,
                  int K,
                  const int* __restrict__ tokbase,
                  const float* __restrict__ cw, float wscale)
{
    int z = blockIdx.z;
    int M = cntp ? cntp[z] : Mdir;
    int row0 = blockIdx.y * BMT;
    if (row0 >= M) return;
    int col0 = blockIdx.x * BNT;

    const float* Az = A + (size_t)z * strideAe;
    const float* Bz = B + (size_t)z * strideBe;
    const int* tokz = (GA || SC) ? (tokbase + (size_t)z * TT) : nullptr;

    __shared__ float As[BKT][BMT + 4];
    __shared__ float Bs[BKT][BNT];

    int tid = threadIdx.x;

    // Precompute A-load row sources (constant across K loop)
    int am[2], asrc[2];
#pragma unroll
    for (int it = 0; it < 2; it++) {
        int lin = tid + it * 256;
        int m = lin >> 2;
        int grow = row0 + m;
        am[it] = m;
        if (grow < M) asrc[it] = GA ? tokz[grow] : grow;
        else          asrc[it] = -1;
    }

    float acc[8][8];
#pragma unroll
    for (int i = 0; i < 8; i++)
#pragma unroll
        for (int j = 0; j < 8; j++) acc[i][j] = 0.f;

    int tx = tid & 15;
    int ty = tid >> 4;

    for (int k0 = 0; k0 < K; k0 += BKT) {
#pragma unroll
        for (int it = 0; it < 2; it++) {
            int lin = tid + it * 256;
            int kq = (lin & 3) * 4;
            float4 v = make_float4(0.f, 0.f, 0.f, 0.f);
            if (asrc[it] >= 0)
                v = *(const float4*)(Az + (size_t)asrc[it] * lda + k0 + kq);
            As[kq + 0][am[it]] = v.x;
            As[kq + 1][am[it]] = v.y;
            As[kq + 2][am[it]] = v.z;
            As[kq + 3][am[it]] = v.w;
        }
#pragma unroll
        for (int it = 0; it < 2; it++) {
            int lin = tid + it * 256;
            int br = lin >> 5;
            int bc = (lin & 31) * 4;
            float4 v = *(const float4*)(Bz + (size_t)(k0 + br) * ldb + col0 + bc);
            *(float4*)&Bs[br][bc] = v;
        }
        __syncthreads();
#pragma unroll
        for (int kk = 0; kk < BKT; kk++) {
            float a[8], b[8];
#pragma unroll
            for (int i = 0; i < 4; i++) { a[i] = As[kk][ty * 4 + i]; a[i + 4] = As[kk][64 + ty * 4 + i]; }
#pragma unroll
            for (int j = 0; j < 4; j++) { b[j] = Bs[kk][tx * 4 + j]; b[j + 4] = Bs[kk][64 + tx * 4 + j]; }
#pragma unroll
            for (int i = 0; i < 8; i++)
#pragma unroll
                for (int j = 0; j < 8; j++)
                    acc[i][j] += a[i] * b[j];
        }
        __syncthreads();
    }

#pragma unroll
    for (int i = 0; i < 8; i++) {
        int r = row0 + (i < 4 ? ty * 4 + i : 64 + ty * 4 + (i - 4));
        if (r >= M) continue;
        if (SC) {
            int t = tokz[r];
            float wt = wscale * cw[(size_t)t * EE + z];
            float* Crow = C + (size_t)t * ldc;
#pragma unroll
            for (int j = 0; j < 8; j++) {
                int c = col0 + (j < 4 ? tx * 4 + j : 64 + tx * 4 + (j - 4));
                atomicAdd(&Crow[c], wt * acc[i][j]);
            }
        } else {
            float* Crow = C + (size_t)z * strideCe + (size_t)r * ldc;
#pragma unroll
            for (int j = 0; j < 8; j++) {
                int c = col0 + (j < 4 ? tx * 4 + j : 64 + tx * 4 + (j - 4));
                Crow[c] = acc[i][j];
            }
        }
    }
}

// ---------------- launcher ----------------
extern "C" void kernel_launch(void* const* d_in, const int* in_sizes, int n_in,
                              void* d_out, int out_size) {
    const float* hs  = (const float*)d_in[0];  // [T,H]
    const float* gw  = (const float*)d_in[1];  // [H,E]
    const float* gb  = (const float*)d_in[2];  // [E]
    const float* wgu = (const float*)d_in[3];  // [E,H,2I]
    const float* wdn = (const float*)d_in[4];  // [E,I,H]
    const float* sgu = (const float*)d_in[5];  // [H,2SI]
    const float* sdn = (const float*)d_in[6];  // [SI,H]
    float* out = (float*)d_out;                // [T,H]

    float *p_gu, *p_h, *p_gus, *p_hs, *p_cw;
    int *p_tok, *p_cnt;
    cudaGetSymbolAddress((void**)&p_gu,  g_gu);
    cudaGetSymbolAddress((void**)&p_h,   g_h);
    cudaGetSymbolAddress((void**)&p_gus, g_gus);
    cudaGetSymbolAddress((void**)&p_hs,  g_hs);
    cudaGetSymbolAddress((void**)&p_cw,  g_cw);
    cudaGetSymbolAddress((void**)&p_tok, g_tok);
    cudaGetSymbolAddress((void**)&p_cnt, g_cnt);

    // 1. router + top-k
    router_kernel<<<TT / 8, dim3(32, 8)>>>(hs, gw, gb);
    // 2. token compaction per expert
    gather_kernel<<<EE, 32>>>();

    // 3. shared expert gate_up: [T,H] x [H,2SI] -> g_gus
    sgemm_kernel<false, false><<<dim3((2 * SSI) / BNT, TT / BMT, 1), 256>>>(
        hs, 0, HH, sgu, 0, 2 * SSI, p_gus, 0, 2 * SSI,
        TT, nullptr, HH, nullptr, nullptr, 0.f);
    // 4. shared activation
    act_shared_kernel<<<(TT * SSI) / 256, 256>>>();
    // 5. shared down: [T,SSI] x [SSI,H] -> out (full overwrite of d_out)
    sgemm_kernel<false, false><<<dim3(HH / BNT, TT / BMT, 1), 256>>>(
        p_hs, 0, SSI, sdn, 0, HH, out, 0, HH,
        TT, nullptr, SSI, nullptr, nullptr, 0.f);

    // 6. routed gate_up (gather A rows by token list): per expert [cnt,H] x [H,2I] -> g_gu
    sgemm_kernel<true, false><<<dim3((2 * II) / BNT, TT / BMT, EE), 256>>>(
        hs, 0, HH,
        wgu, (size_t)HH * 2 * II, 2 * II,
        p_gu, (size_t)TT * 2 * II, 2 * II,
        0, p_cnt, HH, p_tok, nullptr, 0.f);
    // 7. routed activation
    act_exp_kernel<<<dim3(TT, EE), 256>>>();
    // 8. routed down + scaled scatter-add into out: [cnt,I] x [I,H]
    sgemm_kernel<false, true><<<dim3(HH / BNT, TT / BMT, EE), 256>>>(
        p_h, (size_t)TT * II, II,
        wdn, (size_t)II * HH, HH,
        out, 0, HH,
        0, p_cnt, II, p_tok, p_cw, RSCALE);
}

// round 4
// speedup vs baseline: 1.5967x; 1.5967x over previous
#include <cuda_runtime.h>
#include <cuda_bf16.h>
#include <math.h>
#include <stdint.h>

// ---------------- problem constants ----------------
#define TT 4096
#define HH 2048
#define EE 32
#define II 1024
#define TOPK 8
#define NGROUP 8
#define GSIZE 4      // EE / NGROUP
#define TOPKG 4
#define SSI 2048     // shared expert intermediate
#define RSCALE 2.5f

// ---------------- scratch (device globals; no allocs allowed) ----------------
__device__ float g_cw[(size_t)TT * EE];
__device__ int   g_tok[(size_t)EE * TT];
__device__ int   g_cnt[EE];

// bf16 hi/lo splits of inputs & weights
__device__ __nv_bfloat16 s_hs_h [(size_t)TT * HH];
__device__ __nv_bfloat16 s_hs_l [(size_t)TT * HH];
__device__ __nv_bfloat16 s_wgu_h[(size_t)EE * HH * 2 * II];
__device__ __nv_bfloat16 s_wgu_l[(size_t)EE * HH * 2 * II];
__device__ __nv_bfloat16 s_wdn_h[(size_t)EE * II * HH];
__device__ __nv_bfloat16 s_wdn_l[(size_t)EE * II * HH];
__device__ __nv_bfloat16 s_sgu_h[(size_t)HH * 2 * SSI];
__device__ __nv_bfloat16 s_sgu_l[(size_t)HH * 2 * SSI];
__device__ __nv_bfloat16 s_sdn_h[(size_t)SSI * HH];
__device__ __nv_bfloat16 s_sdn_l[(size_t)SSI * HH];

// fp32 gate_up intermediates + bf16 hi/lo activated intermediates
__device__ float g_gu [(size_t)EE * TT * 2 * II];   // 1 GB
__device__ float g_gus[(size_t)TT * 2 * SSI];       // 64 MB
__device__ __nv_bfloat16 g_ha_h[(size_t)EE * TT * II];
__device__ __nv_bfloat16 g_ha_l[(size_t)EE * TT * II];
__device__ __nv_bfloat16 s_hsa_h[(size_t)TT * SSI];
__device__ __nv_bfloat16 s_hsa_l[(size_t)TT * SSI];

// ---------------- router: logits + grouped top-k + dense combine weights ----------------
__global__ void router_kernel(const float* __restrict__ hs,
                              const float* __restrict__ gw,
                              const float* __restrict__ bias) {
    int t    = blockIdx.x * blockDim.y + threadIdx.y;  // one warp per token
    int lane = threadIdx.x;                            // one lane per expert

    const float* hrow = hs + (size_t)t * HH;
    float acc = 0.f;
    for (int h = 0; h < HH; h += 4) {
        float4 hv = *(const float4*)(hrow + h);
        acc += hv.x * gw[(h + 0) * EE + lane];
        acc += hv.y * gw[(h + 1) * EE + lane];
        acc += hv.z * gw[(h + 2) * EE + lane];
        acc += hv.w * gw[(h + 3) * EE + lane];
    }
    float score = 1.f / (1.f + expf(-acc));   // sigmoid
    float sc    = score + bias[lane];         // biased score (selection only)

    __shared__ float s_score[8][32];
    __shared__ float s_sc[8][32];
    s_score[threadIdx.y][lane] = score;
    s_sc[threadIdx.y][lane]    = sc;
    __syncwarp();

    if (lane == 0) {
        float scv[EE], scoresv[EE];
        for (int e = 0; e < EE; e++) { scv[e] = s_sc[threadIdx.y][e]; scoresv[e] = s_score[threadIdx.y][e]; }

        float gs[NGROUP];
        for (int g = 0; g < NGROUP; g++) {
            float m1 = -INFINITY; int i1 = 0;
            for (int j = 0; j < GSIZE; j++) {
                float v = scv[g * GSIZE + j];
                if (v > m1) { m1 = v; i1 = j; }
            }
            float m2 = -INFINITY;
            for (int j = 0; j < GSIZE; j++) {
                if (j != i1) { float v = scv[g * GSIZE + j]; if (v > m2) m2 = v; }
            }
            gs[g] = m1 + m2;
        }
        bool gsel[NGROUP];
        for (int g = 0; g < NGROUP; g++) gsel[g] = false;
        for (int it = 0; it < TOPKG; it++) {
            float best = -INFINITY; int bi = 0;
            for (int g = 0; g < NGROUP; g++)
                if (!gsel[g] && gs[g] > best) { best = gs[g]; bi = g; }
            gsel[bi] = true;
        }
        float masked[EE];
        for (int e = 0; e < EE; e++) masked[e] = gsel[e / GSIZE] ? scv[e] : -INFINITY;
        int   ids[TOPK]; float wv[TOPK]; float wsum = 0.f;
        for (int k = 0; k < TOPK; k++) {
            float best = -INFINITY; int bi = 0;
            for (int e = 0; e < EE; e++)
                if (masked[e] > best) { best = masked[e]; bi = e; }
            masked[bi] = -INFINITY;
            ids[k] = bi; wv[k] = scoresv[bi]; wsum += wv[k];
        }
        float inv = 1.f / (wsum + 1e-20f);
        float row[EE];
        for (int e = 0; e < EE; e++) row[e] = 0.f;
        for (int k = 0; k < TOPK; k++) row[ids[k]] = wv[k] * inv;
        for (int e = 0; e < EE; e++) g_cw[(size_t)t * EE + e] = row[e];
    }
}

// ---------------- per-expert token compaction ----------------
__global__ void gather_kernel() {
    int e = blockIdx.x;
    int lane = threadIdx.x;
    int cnt = 0;
    for (int base = 0; base < TT; base += 32) {
        int t = base + lane;
        bool sel = g_cw[(size_t)t * EE + e] > 0.f;
        unsigned m = __ballot_sync(0xffffffffu, sel);
        int pos = cnt + __popc(m & ((1u << lane) - 1u));
        if (sel) g_tok[(size_t)e * TT + pos] = t;
        cnt += __popc(m);
    }
    if (lane == 0) g_cnt[e] = cnt;
}

// ---------------- fp32 -> bf16 hi/lo split ----------------
__global__ void split_kernel(const float* __restrict__ src,
                             __nv_bfloat16* __restrict__ hi,
                             __nv_bfloat16* __restrict__ lo, size_t n) {
    size_t i = ((size_t)blockIdx.x * blockDim.x + threadIdx.x) * 4;
    if (i >= n) return;
    float4 v = *(const float4*)(src + i);
    float vs[4] = {v.x, v.y, v.z, v.w};
    __nv_bfloat16 hv[4], lv[4];
#pragma unroll
    for (int k = 0; k < 4; k++) {
        __nv_bfloat16 h = __float2bfloat16(vs[k]);
        hv[k] = h;
        lv[k] = __float2bfloat16(vs[k] - __bfloat162float(h));
    }
    *(uint2*)(hi + i) = *(uint2*)hv;
    *(uint2*)(lo + i) = *(uint2*)lv;
}

// ---------------- activations (fp32 -> silu*up -> bf16 hi/lo) ----------------
__global__ void act_shared_kernel() {
    size_t i = ((size_t)blockIdx.x * blockDim.x + threadIdx.x) * 4;  // over TT*SSI
    int t = (int)(i / SSI);
    int j = (int)(i % SSI);
    float4 g4 = *(const float4*)&g_gus[(size_t)t * 2 * SSI + j];
    float4 u4 = *(const float4*)&g_gus[(size_t)t * 2 * SSI + SSI + j];
    float gv[4] = {g4.x, g4.y, g4.z, g4.w};
    float uv[4] = {u4.x, u4.y, u4.z, u4.w};
    __nv_bfloat16 hv[4], lv[4];
#pragma unroll
    for (int k = 0; k < 4; k++) {
        float h = uv[k] * (gv[k] / (1.f + expf(-gv[k])));
        __nv_bfloat16 hb = __float2bfloat16(h);
        hv[k] = hb;
        lv[k] = __float2bfloat16(h - __bfloat162float(hb));
    }
    *(uint2*)(s_hsa_h + (size_t)t * SSI + j) = *(uint2*)hv;
    *(uint2*)(s_hsa_l + (size_t)t * SSI + j) = *(uint2*)lv;
}

__global__ void act_exp_kernel() {
    int e = blockIdx.y;
    int slot = blockIdx.x;
    if (slot >= g_cnt[e]) return;
    size_t gbase = ((size_t)e * TT + slot) * (2 * II);
    size_t hbase = ((size_t)e * TT + slot) * II;
    int j = threadIdx.x * 4;  // 256 threads * 4 = II
    float4 g4 = *(const float4*)&g_gu[gbase + j];
    float4 u4 = *(const float4*)&g_gu[gbase + II + j];
    float gv[4] = {g4.x, g4.y, g4.z, g4.w};
    float uv[4] = {u4.x, u4.y, u4.z, u4.w};
    __nv_bfloat16 hv[4], lv[4];
#pragma unroll
    for (int k = 0; k < 4; k++) {
        float h = uv[k] * (gv[k] / (1.f + expf(-gv[k])));
        __nv_bfloat16 hb = __float2bfloat16(h);
        hv[k] = hb;
        lv[k] = __float2bfloat16(h - __bfloat162float(hb));
    }
    *(uint2*)(g_ha_h + hbase + j) = *(uint2*)hv;
    *(uint2*)(g_ha_l + hbase + j) = *(uint2*)lv;
}

// ---------------- tensor-core GEMM (bf16 split x3, fp32 acc) ----------------
#define PA 40          // A smem pitch (bf16 elems): 80B rows, ldmatrix conflict-free
#define PB 136         // B smem pitch: 272B rows
#define ASZ (128 * PA)
#define BSZ (32 * PB)
#define STG (2 * ASZ + 2 * BSZ)     // elems per stage (A hi/lo + B hi/lo)
#define SMEM_BYTES (2 * STG * 2)    // 2 stages, bf16

__device__ __forceinline__ void cp16(uint32_t dst, const void* src, int sz) {
    asm volatile("cp.async.cg.shared.global [%0], [%1], 16, %2;\n"
                 :: "r"(dst), "l"(src), "r"(sz));
}
__device__ __forceinline__ void cpcommit() { asm volatile("cp.async.commit_group;\n"); }
template<int N> __device__ __forceinline__ void cpwait() {
    asm volatile("cp.async.wait_group %0;\n" :: "n"(N));
}
__device__ __forceinline__ void ldsm4(uint32_t* r, uint32_t addr) {
    asm volatile("ldmatrix.sync.aligned.m8n8.x4.shared.b16 {%0,%1,%2,%3}, [%4];"
                 : "=r"(r[0]), "=r"(r[1]), "=r"(r[2]), "=r"(r[3]) : "r"(addr));
}
__device__ __forceinline__ void ldsm4t(uint32_t* r, uint32_t addr) {
    asm volatile("ldmatrix.sync.aligned.m8n8.x4.trans.shared.b16 {%0,%1,%2,%3}, [%4];"
                 : "=r"(r[0]), "=r"(r[1]), "=r"(r[2]), "=r"(r[3]) : "r"(addr));
}
__device__ __forceinline__ void mmabf16(float* c, const uint32_t* a, uint32_t b0, uint32_t b1) {
    asm volatile("mma.sync.aligned.m16n8k16.row.col.f32.bf16.bf16.f32 "
                 "{%0,%1,%2,%3}, {%4,%5,%6,%7}, {%8,%9}, {%0,%1,%2,%3};"
                 : "+f"(c[0]), "+f"(c[1]), "+f"(c[2]), "+f"(c[3])
                 : "r"(a[0]), "r"(a[1]), "r"(a[2]), "r"(a[3]), "r"(b0), "r"(b1));
}

// GA: gather A rows via token list; SC: scatter-add C rows via token list * weight
template<bool GA, bool SC>
__global__ __launch_bounds__(256, 2)
void bgemm(const __nv_bfloat16* __restrict__ Ah, const __nv_bfloat16* __restrict__ Al,
           size_t strideAe, int lda,
           const __nv_bfloat16* __restrict__ Bh, const __nv_bfloat16* __restrict__ Bl,
           size_t strideBe, int ldb,
           float* __restrict__ C, size_t strideCe, int ldc,
           int Mdir, const int* __restrict__ cntp, int K,
           const int* __restrict__ tokall,
           const float* __restrict__ cw, float wscale)
{
    extern __shared__ __nv_bfloat16 sm[];
    int z = blockIdx.z;
    int M = cntp ? cntp[z] : Mdir;
    int row0 = blockIdx.y * 128;
    if (row0 >= M) return;
    int col0 = blockIdx.x * 128;

    const __nv_bfloat16* Ahz = Ah + (size_t)z * strideAe;
    const __nv_bfloat16* Alz = Al + (size_t)z * strideAe;
    const __nv_bfloat16* Bhz = Bh + (size_t)z * strideBe;
    const __nv_bfloat16* Blz = Bl + (size_t)z * strideBe;
    const int* tokz = (GA || SC) ? tokall + (size_t)z * TT : nullptr;

    int tid = threadIdx.x;
    uint32_t sbase = (uint32_t)__cvta_generic_to_shared(sm);

    long asrc[2];
#pragma unroll
    for (int it = 0; it < 2; it++) {
        int q = tid + it * 256;
        int m = q >> 2;
        int grow = row0 + m;
        if (grow < M) asrc[it] = GA ? (long)tokz[grow] : (long)grow;
        else          asrc[it] = -1;
    }

    auto load_stage = [&](int kt, int s) {
        uint32_t base = sbase + (uint32_t)(s * STG) * 2;
#pragma unroll
        for (int it = 0; it < 2; it++) {
            int q = tid + it * 256;
            int m = q >> 2, seg = q & 3;
            uint32_t doff = (uint32_t)(m * PA + seg * 8) * 2;
            int sz = asrc[it] >= 0 ? 16 : 0;
            const __nv_bfloat16* ph = asrc[it] >= 0 ? Ahz + (size_t)asrc[it] * lda + kt * 32 + seg * 8 : Ahz;
            const __nv_bfloat16* pl = asrc[it] >= 0 ? Alz + (size_t)asrc[it] * lda + kt * 32 + seg * 8 : Alz;
            cp16(base + doff, ph, sz);
            cp16(base + (uint32_t)ASZ * 2 + doff, pl, sz);
        }
#pragma unroll
        for (int it = 0; it < 2; it++) {
            int q = tid + it * 256;
            int kb = q >> 4, seg = q & 15;
            uint32_t doff = (uint32_t)(kb * PB + seg * 8) * 2;
            size_t goff = (size_t)(kt * 32 + kb) * ldb + col0 + seg * 8;
            cp16(base + (uint32_t)(2 * ASZ) * 2 + doff, Bhz + goff, 16);
            cp16(base + (uint32_t)(2 * ASZ + BSZ) * 2 + doff, Blz + goff, 16);
        }
        cpcommit();
    };

    int lane = tid & 31, wid = tid >> 5;
    int wm = wid & 3, wn = wid >> 2;   // 4 warps along M (32 rows), 2 along N (64 cols)

    float acc[2][8][4];
#pragma unroll
    for (int a = 0; a < 2; a++)
#pragma unroll
        for (int b = 0; b < 8; b++)
#pragma unroll
            for (int c = 0; c < 4; c++) acc[a][b][c] = 0.f;

    int NT = K / 32;
    load_stage(0, 0);
    for (int kt = 0; kt < NT; kt++) {
        int s = kt & 1;
        if (kt + 1 < NT) { load_stage(kt + 1, (kt + 1) & 1); cpwait<1>(); }
        else             { cpwait<0>(); }
        __syncthreads();
        uint32_t base = sbase + (uint32_t)(s * STG) * 2;
#pragma unroll
        for (int s2 = 0; s2 < 2; s2++) {
            int k0 = s2 * 16;
            uint32_t a_h[2][4], a_l[2][4];
            int arow = lane & 15;
            int achk = lane >> 4;
#pragma unroll
            for (int mt = 0; mt < 2; mt++) {
                uint32_t off = (uint32_t)((wm * 32 + mt * 16 + arow) * PA + k0 + achk * 8) * 2;
                ldsm4(a_h[mt], base + off);
                ldsm4(a_l[mt], base + (uint32_t)ASZ * 2 + off);
            }
#pragma unroll
            for (int nt = 0; nt < 4; nt++) {
                int n0 = wn * 64 + nt * 16;
                uint32_t boff = (uint32_t)((k0 + (lane & 15)) * PB + n0 + (lane >> 4) * 8) * 2;
                uint32_t b_h[4], b_l[4];
                ldsm4t(b_h, base + (uint32_t)(2 * ASZ) * 2 + boff);
                ldsm4t(b_l, base + (uint32_t)(2 * ASZ + BSZ) * 2 + boff);
#pragma unroll
                for (int mt = 0; mt < 2; mt++) {
#pragma unroll
                    for (int j = 0; j < 2; j++) {
                        float* c = acc[mt][nt * 2 + j];
                        mmabf16(c, a_h[mt], b_h[2 * j], b_h[2 * j + 1]);
                        mmabf16(c, a_h[mt], b_l[2 * j], b_l[2 * j + 1]);
                        mmabf16(c, a_l[mt], b_h[2 * j], b_h[2 * j + 1]);
                    }
                }
            }
        }
        __syncthreads();
    }

    // epilogue
    int r_base = row0 + wm * 32 + (lane >> 2);
    int c_base = col0 + wn * 64 + (lane & 3) * 2;
#pragma unroll
    for (int mt = 0; mt < 2; mt++) {
#pragma unroll
        for (int half = 0; half < 2; half++) {
            int r = r_base + mt * 16 + half * 8;
            if (r >= M) continue;
            if (SC) {
                int t = tokz[r];
                float wt = wscale * cw[(size_t)t * EE + z];
                float* Crow = C + (size_t)t * ldc;
#pragma unroll
                for (int nt = 0; nt < 8; nt++) {
                    int c = c_base + nt * 8;
                    atomicAdd(&Crow[c],     wt * acc[mt][nt][half * 2 + 0]);
                    atomicAdd(&Crow[c + 1], wt * acc[mt][nt][half * 2 + 1]);
                }
            } else {
                float* Crow = C + (size_t)z * strideCe + (size_t)r * ldc;
#pragma unroll
                for (int nt = 0; nt < 8; nt++) {
                    int c = c_base + nt * 8;
                    float2 v = make_float2(acc[mt][nt][half * 2 + 0], acc[mt][nt][half * 2 + 1]);
                    *(float2*)&Crow[c] = v;
                }
            }
        }
    }
}

// ---------------- launcher ----------------
extern "C" void kernel_launch(void* const* d_in, const int* in_sizes, int n_in,
                              void* d_out, int out_size) {
    const float* hs  = (const float*)d_in[0];  // [T,H]
    const float* gw  = (const float*)d_in[1];  // [H,E]
    const float* gb  = (const float*)d_in[2];  // [E]
    const float* wgu = (const float*)d_in[3];  // [E,H,2I]
    const float* wdn = (const float*)d_in[4];  // [E,I,H]
    const float* sgu = (const float*)d_in[5];  // [H,2SI]
    const float* sdn = (const float*)d_in[6];  // [SI,H]
    float* out = (float*)d_out;                // [T,H]

    cudaFuncSetAttribute((const void*)bgemm<false, false>,
                         cudaFuncAttributeMaxDynamicSharedMemorySize, SMEM_BYTES);
    cudaFuncSetAttribute((const void*)bgemm<true, false>,
                         cudaFuncAttributeMaxDynamicSharedMemorySize, SMEM_BYTES);
    cudaFuncSetAttribute((const void*)bgemm<false, true>,
                         cudaFuncAttributeMaxDynamicSharedMemorySize, SMEM_BYTES);

    __nv_bfloat16 *p_hs_h, *p_hs_l, *p_wgu_h, *p_wgu_l, *p_wdn_h, *p_wdn_l;
    __nv_bfloat16 *p_sgu_h, *p_sgu_l, *p_sdn_h, *p_sdn_l;
    __nv_bfloat16 *p_ha_h, *p_ha_l, *p_hsa_h, *p_hsa_l;
    float *p_gu, *p_gus, *p_cw;
    int *p_tok, *p_cnt;
    cudaGetSymbolAddress((void**)&p_hs_h,  s_hs_h);
    cudaGetSymbolAddress((void**)&p_hs_l,  s_hs_l);
    cudaGetSymbolAddress((void**)&p_wgu_h, s_wgu_h);
    cudaGetSymbolAddress((void**)&p_wgu_l, s_wgu_l);
    cudaGetSymbolAddress((void**)&p_wdn_h, s_wdn_h);
    cudaGetSymbolAddress((void**)&p_wdn_l, s_wdn_l);
    cudaGetSymbolAddress((void**)&p_sgu_h, s_sgu_h);
    cudaGetSymbolAddress((void**)&p_sgu_l, s_sgu_l);
    cudaGetSymbolAddress((void**)&p_sdn_h, s_sdn_h);
    cudaGetSymbolAddress((void**)&p_sdn_l, s_sdn_l);
    cudaGetSymbolAddress((void**)&p_ha_h,  g_ha_h);
    cudaGetSymbolAddress((void**)&p_ha_l,  g_ha_l);
    cudaGetSymbolAddress((void**)&p_hsa_h, s_hsa_h);
    cudaGetSymbolAddress((void**)&p_hsa_l, s_hsa_l);
    cudaGetSymbolAddress((void**)&p_gu,    g_gu);
    cudaGetSymbolAddress((void**)&p_gus,   g_gus);
    cudaGetSymbolAddress((void**)&p_cw,    g_cw);
    cudaGetSymbolAddress((void**)&p_tok,   g_tok);
    cudaGetSymbolAddress((void**)&p_cnt,   g_cnt);

    // 0. bf16 hi/lo splits
    auto blocks = [](size_t n) { return (unsigned)(n / 4 / 256); };
    split_kernel<<<blocks((size_t)TT * HH), 256>>>(hs, p_hs_h, p_hs_l, (size_t)TT * HH);
    split_kernel<<<blocks((size_t)EE * HH * 2 * II), 256>>>(wgu, p_wgu_h, p_wgu_l, (size_t)EE * HH * 2 * II);
    split_kernel<<<blocks((size_t)EE * II * HH), 256>>>(wdn, p_wdn_h, p_wdn_l, (size_t)EE * II * HH);
    split_kernel<<<blocks((size_t)HH * 2 * SSI), 256>>>(sgu, p_sgu_h, p_sgu_l, (size_t)HH * 2 * SSI);
    split_kernel<<<blocks((size_t)SSI * HH), 256>>>(sdn, p_sdn_h, p_sdn_l, (size_t)SSI * HH);

    // 1. router + top-k; 2. compaction
    router_kernel<<<TT / 8, dim3(32, 8)>>>(hs, gw, gb);
    gather_kernel<<<EE, 32>>>();

    // 3. shared gate_up: [T,H] x [H,2SI] -> g_gus (fp32)
    bgemm<false, false><<<dim3((2 * SSI) / 128, TT / 128, 1), 256, SMEM_BYTES>>>(
        p_hs_h, p_hs_l, 0, HH,
        p_sgu_h, p_sgu_l, 0, 2 * SSI,
        p_gus, 0, 2 * SSI,
        TT, nullptr, HH, nullptr, nullptr, 0.f);
    // 4. shared activation -> bf16 hi/lo
    act_shared_kernel<<<(TT * SSI) / (256 * 4), 256>>>();
    // 5. shared down: [T,SSI] x [SSI,H] -> out (overwrites poison)
    bgemm<false, false><<<dim3(HH / 128, TT / 128, 1), 256, SMEM_BYTES>>>(
        p_hsa_h, p_hsa_l, 0, SSI,
        p_sdn_h, p_sdn_l, 0, HH,
        out, 0, HH,
        TT, nullptr, SSI, nullptr, nullptr, 0.f);

    // 6. routed gate_up (gather rows): per expert [cnt,H] x [H,2I] -> g_gu (fp32)
    bgemm<true, false><<<dim3((2 * II) / 128, TT / 128, EE), 256, SMEM_BYTES>>>(
        p_hs_h, p_hs_l, 0, HH,
        p_wgu_h, p_wgu_l, (size_t)HH * 2 * II, 2 * II,
        p_gu, (size_t)TT * 2 * II, 2 * II,
        0, p_cnt, HH, p_tok, nullptr, 0.f);
    // 7. routed activation -> bf16 hi/lo
    act_exp_kernel<<<dim3(TT, EE), 256>>>();
    // 8. routed down + scaled scatter-add: [cnt,I] x [I,H] -> out
    bgemm<false, true><<<dim3(HH / 128, TT / 128, EE), 256, SMEM_BYTES>>>(
        p_ha_h, p_ha_l, (size_t)TT * II, II,
        p_wdn_h, p_wdn_l, (size_t)II * HH, HH,
        out, 0, HH,
        0, p_cnt, II, p_tok, p_cw, RSCALE);
}

// round 6
// speedup vs baseline: 3.3791x; 2.1163x over previous
#include <cuda_runtime.h>
#include <cuda_fp16.h>
#include <math.h>
#include <stdint.h>

// ---------------- problem constants ----------------
#define TT 4096
#define HH 2048
#define EE 32
#define II 1024
#define TOPK 8
#define NGROUP 8
#define GSIZE 4
#define TOPKG 4
#define SSI 2048
#define RSCALE 2.5f

// ---------------- scratch (device globals) ----------------
__device__ float g_cw[(size_t)TT * EE];
__device__ int   g_tok[(size_t)EE * TT];
__device__ int   g_cnt[EE];

// fp16 operands. A-side (hidden / activated) split hi+lo; weights single fp16.
__device__ __half s_hs_h [(size_t)TT * HH];
__device__ __half s_hs_l [(size_t)TT * HH];
__device__ __half s_wgu  [(size_t)EE * HH * 2 * II];   // [e][k=H][n'=2I] gate/up interleaved
__device__ __half s_wdn  [(size_t)EE * II * HH];       // [e][k=I][n=H]
__device__ __half s_sgu  [(size_t)HH * 2 * SSI];       // [k=H][n'=2SI] interleaved
__device__ __half s_sdn  [(size_t)SSI * HH];           // [k=SI][n=H]

// activated intermediates (fp16 hi/lo), row-major [*, I]
__device__ __half g_ha_h[(size_t)EE * TT * II];
__device__ __half g_ha_l[(size_t)EE * TT * II];
__device__ __half s_hsa_h[(size_t)TT * SSI];
__device__ __half s_hsa_l[(size_t)TT * SSI];

// ---------------- router ----------------
__global__ void router_kernel(const float* __restrict__ hs,
                              const float* __restrict__ gw,
                              const float* __restrict__ bias) {
    int t    = blockIdx.x * blockDim.y + threadIdx.y;
    int lane = threadIdx.x;
    const float* hrow = hs + (size_t)t * HH;
    float acc = 0.f;
    for (int h = 0; h < HH; h += 4) {
        float4 hv = *(const float4*)(hrow + h);
        acc += hv.x * gw[(h + 0) * EE + lane];
        acc += hv.y * gw[(h + 1) * EE + lane];
        acc += hv.z * gw[(h + 2) * EE + lane];
        acc += hv.w * gw[(h + 3) * EE + lane];
    }
    float score = 1.f / (1.f + expf(-acc));
    float sc    = score + bias[lane];
    __shared__ float s_score[8][32];
    __shared__ float s_sc[8][32];
    s_score[threadIdx.y][lane] = score;
    s_sc[threadIdx.y][lane]    = sc;
    __syncwarp();
    if (lane == 0) {
        float scv[EE], scoresv[EE];
        for (int e = 0; e < EE; e++) { scv[e] = s_sc[threadIdx.y][e]; scoresv[e] = s_score[threadIdx.y][e]; }
        float gs[NGROUP];
        for (int g = 0; g < NGROUP; g++) {
            float m1 = -INFINITY; int i1 = 0;
            for (int j = 0; j < GSIZE; j++) {
                float v = scv[g * GSIZE + j];
                if (v > m1) { m1 = v; i1 = j; }
            }
            float m2 = -INFINITY;
            for (int j = 0; j < GSIZE; j++)
                if (j != i1) { float v = scv[g * GSIZE + j]; if (v > m2) m2 = v; }
            gs[g] = m1 + m2;
        }
        bool gsel[NGROUP];
        for (int g = 0; g < NGROUP; g++) gsel[g] = false;
        for (int it = 0; it < TOPKG; it++) {
            float best = -INFINITY; int bi = 0;
            for (int g = 0; g < NGROUP; g++)
                if (!gsel[g] && gs[g] > best) { best = gs[g]; bi = g; }
            gsel[bi] = true;
        }
        float masked[EE];
        for (int e = 0; e < EE; e++) masked[e] = gsel[e / GSIZE] ? scv[e] : -INFINITY;
        int ids[TOPK]; float wv[TOPK]; float wsum = 0.f;
        for (int k = 0; k < TOPK; k++) {
            float best = -INFINITY; int bi = 0;
            for (int e = 0; e < EE; e++)
                if (masked[e] > best) { best = masked[e]; bi = e; }
            masked[bi] = -INFINITY;
            ids[k] = bi; wv[k] = scoresv[bi]; wsum += wv[k];
        }
        float inv = 1.f / (wsum + 1e-20f);
        float row[EE];
        for (int e = 0; e < EE; e++) row[e] = 0.f;
        for (int k = 0; k < TOPK; k++) row[ids[k]] = wv[k] * inv;
        for (int e = 0; e < EE; e++) g_cw[(size_t)t * EE + e] = row[e];
    }
}

__global__ void gather_kernel() {
    int e = blockIdx.x;
    int lane = threadIdx.x;
    int cnt = 0;
    for (int base = 0; base < TT; base += 32) {
        int t = base + lane;
        bool sel = g_cw[(size_t)t * EE + e] > 0.f;
        unsigned m = __ballot_sync(0xffffffffu, sel);
        int pos = cnt + __popc(m & ((1u << lane) - 1u));
        if (sel) g_tok[(size_t)e * TT + pos] = t;
        cnt += __popc(m);
    }
    if (lane == 0) g_cnt[e] = cnt;
}

// ---------------- fp32 -> fp16 hi/lo split (A side) ----------------
__global__ void split_kernel(const float* __restrict__ src,
                             __half* __restrict__ hi,
                             __half* __restrict__ lo, size_t n) {
    size_t i = ((size_t)blockIdx.x * blockDim.x + threadIdx.x) * 4;
    if (i >= n) return;
    float4 v = *(const float4*)(src + i);
    float vs[4] = {v.x, v.y, v.z, v.w};
    __half hv[4], lv[4];
#pragma unroll
    for (int k = 0; k < 4; k++) {
        __half h = __float2half_rn(vs[k]);
        hv[k] = h;
        lv[k] = __float2half_rn(vs[k] - __half2float(h));
    }
    *(uint2*)(hi + i) = *(uint2*)hv;
    *(uint2*)(lo + i) = *(uint2*)lv;
}

// ---------------- fp32 -> fp16 plain convert (weights) ----------------
__global__ void conv_kernel(const float* __restrict__ src, __half* __restrict__ dst, size_t n) {
    size_t i = ((size_t)blockIdx.x * blockDim.x + threadIdx.x) * 4;
    if (i >= n) return;
    float4 v = *(const float4*)(src + i);
    __half hv[4] = {__float2half_rn(v.x), __float2half_rn(v.y),
                    __float2half_rn(v.z), __float2half_rn(v.w)};
    *(uint2*)(dst + i) = *(uint2*)hv;
}

// ---------------- fp32 -> fp16 with gate/up column interleave ----------------
// src [e][K][N]; dst column np = 2n (n<half) or 2(n-half)+1
__global__ void conv_ilv_kernel(const float* __restrict__ src, __half* __restrict__ dst,
                                int N, int half, size_t sE, size_t dE) {
    int e = blockIdx.z;
    int row = blockIdx.y;
    int n = (blockIdx.x * blockDim.x + threadIdx.x) * 4;
    const float* S = src + (size_t)e * sE + (size_t)row * N;
    __half* D = dst + (size_t)e * dE + (size_t)row * N;
    float4 v = *(const float4*)(S + n);
    float vs[4] = {v.x, v.y, v.z, v.w};
#pragma unroll
    for (int j = 0; j < 4; j++) {
        int nn = n + j;
        int np = (nn < half) ? 2 * nn : 2 * (nn - half) + 1;
        D[np] = __float2half_rn(vs[j]);
    }
}

// ---------------- mma.sync fp16 GEMM, A = hi+lo split, B single ----------------
#define PA 72          // A smem row pitch (elems), BK=64 + 8 pad
#define PB 136         // B smem row pitch (elems), 128 cols + 8 pad
#define BK 64
#define ASZB (128 * PA * 2)        // bytes per A matrix per stage (18432)
#define BSZB (BK * PB * 2)         // bytes per B per stage (17408)
#define STAGE_B (2 * ASZB + BSZB)  // 54272
#define SMEM_BYTES (2 * STAGE_B)

__device__ __forceinline__ void cp16(uint32_t dst, const void* src, int sz) {
    asm volatile("cp.async.cg.shared.global [%0], [%1], 16, %2;\n"
                 :: "r"(dst), "l"(src), "r"(sz));
}
__device__ __forceinline__ void cpcommit() { asm volatile("cp.async.commit_group;\n"); }
template<int N> __device__ __forceinline__ void cpwait() {
    asm volatile("cp.async.wait_group %0;\n" :: "n"(N));
}
__device__ __forceinline__ void ldsm4(uint32_t* r, uint32_t addr) {
    asm volatile("ldmatrix.sync.aligned.m8n8.x4.shared.b16 {%0,%1,%2,%3}, [%4];"
                 : "=r"(r[0]), "=r"(r[1]), "=r"(r[2]), "=r"(r[3]) : "r"(addr));
}
__device__ __forceinline__ void ldsm4t(uint32_t* r, uint32_t addr) {
    asm volatile("ldmatrix.sync.aligned.m8n8.x4.trans.shared.b16 {%0,%1,%2,%3}, [%4];"
                 : "=r"(r[0]), "=r"(r[1]), "=r"(r[2]), "=r"(r[3]) : "r"(addr));
}
__device__ __forceinline__ void mmaf16(float* c, const uint32_t* a, uint32_t b0, uint32_t b1) {
    asm volatile("mma.sync.aligned.m16n8k16.row.col.f32.f16.f16.f32 "
                 "{%0,%1,%2,%3}, {%4,%5,%6,%7}, {%8,%9}, {%0,%1,%2,%3};"
                 : "+f"(c[0]), "+f"(c[1]), "+f"(c[2]), "+f"(c[3])
                 : "r"(a[0]), "r"(a[1]), "r"(a[2]), "r"(a[3]), "r"(b0), "r"(b1));
}

// GA: gather A rows by token list.
// EPI: 0 plain fp32 store; 1 silu(gate)*up -> fp16 hi/lo (interleaved cols); 2 weighted atomicAdd scatter
template<bool GA, int EPI>
__global__ __launch_bounds__(256, 2)
void hgemm(const __half* __restrict__ Ah, const __half* __restrict__ Al,
           size_t sAe, int lda,
           const __half* __restrict__ B, size_t sBe, int ldb,
           float* __restrict__ C, int ldc,
           __half* __restrict__ Dh, __half* __restrict__ Dl, size_t sDe, int ldd,
           int Mdir, const int* __restrict__ cntp, int K,
           const int* __restrict__ tokall,
           const float* __restrict__ cw, float wscale)
{
    extern __shared__ char smraw[];
    int z = blockIdx.z;
    int M = cntp ? cntp[z] : Mdir;
    int row0 = blockIdx.y * 128;
    if (row0 >= M) return;
    int col0 = blockIdx.x * 128;

    const __half* Ahz = Ah + (size_t)z * sAe;
    const __half* Alz = Al + (size_t)z * sAe;
    const __half* Bz  = B  + (size_t)z * sBe;
    const int* tokz = (GA || EPI == 2) ? tokall + (size_t)z * TT : nullptr;

    int tid = threadIdx.x;
    uint32_t sb = (uint32_t)__cvta_generic_to_shared(smraw);

    // A rows handled by this thread: rows (tid>>3)+32*it, seg (tid&7)*8 elems
    long aRow[4];
    int r0t = tid >> 3;
    int seg = (tid & 7) * 8;
#pragma unroll
    for (int it = 0; it < 4; it++) {
        int grow = row0 + r0t + 32 * it;
        if (grow < M) aRow[it] = GA ? (long)tokz[grow] : (long)grow;
        else          aRow[it] = -1;
    }

    auto load_stage = [&](int kt, int s) {
        uint32_t base = sb + (uint32_t)s * STAGE_B;
#pragma unroll
        for (int it = 0; it < 4; it++) {
            int r = r0t + 32 * it;
            uint32_t d = base + (uint32_t)(r * PA + seg) * 2;
            long src = aRow[it];
            const __half* ph = (src >= 0) ? Ahz + (size_t)src * lda + kt * BK + seg : Ahz;
            const __half* pl = (src >= 0) ? Alz + (size_t)src * lda + kt * BK + seg : Alz;
            int sz = (src >= 0) ? 16 : 0;
            cp16(d, ph, sz);
            cp16(d + ASZB, pl, sz);
        }
        // B: 64 rows x 128 cols; thread covers (q>>4) row, (q&15) seg
#pragma unroll
        for (int it = 0; it < 4; it++) {
            int q = tid + it * 256;
            int kr = q >> 4;
            int ns = (q & 15) * 8;
            uint32_t d = base + 2 * ASZB + (uint32_t)(kr * PB + ns) * 2;
            cp16(d, Bz + (size_t)(kt * BK + kr) * ldb + col0 + ns, 16);
        }
        cpcommit();
    };

    int lane = tid & 31, wid = tid >> 5;
    int wm = wid & 3, wn = wid >> 2;   // 4 warps M (32 rows each), 2 warps N (64 cols each)

    float acc[2][8][4];
#pragma unroll
    for (int a = 0; a < 2; a++)
#pragma unroll
        for (int b = 0; b < 8; b++)
#pragma unroll
            for (int c = 0; c < 4; c++) acc[a][b][c] = 0.f;

    int NT = K / BK;
    load_stage(0, 0);
    for (int kt = 0; kt < NT; kt++) {
        int s = kt & 1;
        if (kt + 1 < NT) { load_stage(kt + 1, (kt + 1) & 1); cpwait<1>(); }
        else             { cpwait<0>(); }
        __syncthreads();
        uint32_t base = sb + (uint32_t)s * STAGE_B;
        int arow = lane & 15;
        int achk = lane >> 4;
#pragma unroll
        for (int s2 = 0; s2 < 4; s2++) {
            int k0 = s2 * 16;
            uint32_t a_h[2][4], a_l[2][4];
#pragma unroll
            for (int mt = 0; mt < 2; mt++) {
                uint32_t off = (uint32_t)((wm * 32 + mt * 16 + arow) * PA + k0 + achk * 8) * 2;
                ldsm4(a_h[mt], base + off);
                ldsm4(a_l[mt], base + ASZB + off);
            }
#pragma unroll
            for (int nt = 0; nt < 4; nt++) {
                uint32_t boff = (uint32_t)((k0 + arow) * PB + wn * 64 + nt * 16 + achk * 8) * 2;
                uint32_t bfr[4];
                ldsm4t(bfr, base + 2 * ASZB + boff);
#pragma unroll
                for (int mt = 0; mt < 2; mt++) {
#pragma unroll
                    for (int j = 0; j < 2; j++) {
                        float* c = acc[mt][nt * 2 + j];
                        mmaf16(c, a_h[mt], bfr[2 * j], bfr[2 * j + 1]);
                        mmaf16(c, a_l[mt], bfr[2 * j], bfr[2 * j + 1]);
                    }
                }
            }
        }
        __syncthreads();
    }

    // ---------------- epilogue ----------------
    int r_base = row0 + wm * 32 + (lane >> 2);
    int c_base = col0 + wn * 64 + (lane & 3) * 2;
#pragma unroll
    for (int mt = 0; mt < 2; mt++) {
#pragma unroll
        for (int half = 0; half < 2; half++) {
            int r = r_base + mt * 16 + half * 8;
            if (r >= M) continue;
            if (EPI == 0) {
                float* Crow = C + (size_t)r * ldc;
#pragma unroll
                for (int q = 0; q < 8; q++) {
                    int c = c_base + q * 8;
                    float2 v = make_float2(acc[mt][q][half * 2 + 0], acc[mt][q][half * 2 + 1]);
                    *(float2*)&Crow[c] = v;
                }
            } else if (EPI == 1) {
                // even col = gate, odd col = up (interleaved weights)
                int cb2 = (c_base >> 1);   // output col = c/2
                __half* DhR = Dh + (size_t)z * sDe + (size_t)r * ldd;
                __half* DlR = Dl + (size_t)z * sDe + (size_t)r * ldd;
#pragma unroll
                for (int q = 0; q < 8; q++) {
                    float g = acc[mt][q][half * 2 + 0];
                    float u = acc[mt][q][half * 2 + 1];
                    float h = u * (g / (1.f + expf(-g)));
                    __half hb = __float2half_rn(h);
                    __half lb = __float2half_rn(h - __half2float(hb));
                    int c2 = cb2 + q * 4;
                    DhR[c2] = hb;
                    DlR[c2] = lb;
                }
            } else {  // EPI == 2
                int t = tokz[r];
                float wt = wscale * cw[(size_t)t * EE + z];
                float* Crow = C + (size_t)t * ldc;
#pragma unroll
                for (int q = 0; q < 8; q++) {
                    int c = c_base + q * 8;
                    atomicAdd(&Crow[c],     wt * acc[mt][q][half * 2 + 0]);
                    atomicAdd(&Crow[c + 1], wt * acc[mt][q][half * 2 + 1]);
                }
            }
        }
    }
}

// ---------------- launcher ----------------
extern "C" void kernel_launch(void* const* d_in, const int* in_sizes, int n_in,
                              void* d_out, int out_size) {
    const float* hs  = (const float*)d_in[0];
    const float* gw  = (const float*)d_in[1];
    const float* gb  = (const float*)d_in[2];
    const float* wgu = (const float*)d_in[3];  // [E,H,2I]
    const float* wdn = (const float*)d_in[4];  // [E,I,H]
    const float* sgu = (const float*)d_in[5];  // [H,2SI]
    const float* sdn = (const float*)d_in[6];  // [SI,H]
    float* out = (float*)d_out;

    cudaFuncSetAttribute((const void*)hgemm<false, 0>, cudaFuncAttributeMaxDynamicSharedMemorySize, SMEM_BYTES);
    cudaFuncSetAttribute((const void*)hgemm<false, 1>, cudaFuncAttributeMaxDynamicSharedMemorySize, SMEM_BYTES);
    cudaFuncSetAttribute((const void*)hgemm<true,  1>, cudaFuncAttributeMaxDynamicSharedMemorySize, SMEM_BYTES);
    cudaFuncSetAttribute((const void*)hgemm<false, 2>, cudaFuncAttributeMaxDynamicSharedMemorySize, SMEM_BYTES);

    __half *p_hs_h, *p_hs_l, *p_wgu, *p_wdn, *p_sgu, *p_sdn;
    __half *p_ha_h, *p_ha_l, *p_hsa_h, *p_hsa_l;
    float *p_cw;
    int *p_tok, *p_cnt;
    cudaGetSymbolAddress((void**)&p_hs_h,  s_hs_h);
    cudaGetSymbolAddress((void**)&p_hs_l,  s_hs_l);
    cudaGetSymbolAddress((void**)&p_wgu,   s_wgu);
    cudaGetSymbolAddress((void**)&p_wdn,   s_wdn);
    cudaGetSymbolAddress((void**)&p_sgu,   s_sgu);
    cudaGetSymbolAddress((void**)&p_sdn,   s_sdn);
    cudaGetSymbolAddress((void**)&p_ha_h,  g_ha_h);
    cudaGetSymbolAddress((void**)&p_ha_l,  g_ha_l);
    cudaGetSymbolAddress((void**)&p_hsa_h, s_hsa_h);
    cudaGetSymbolAddress((void**)&p_hsa_l, s_hsa_l);
    cudaGetSymbolAddress((void**)&p_cw,    g_cw);
    cudaGetSymbolAddress((void**)&p_tok,   g_tok);
    cudaGetSymbolAddress((void**)&p_cnt,   g_cnt);

    // 0. conversions
    split_kernel<<<(unsigned)((size_t)TT * HH / 4 / 256), 256>>>(hs, p_hs_h, p_hs_l, (size_t)TT * HH);
    conv_ilv_kernel<<<dim3((2 * II) / (4 * 256), HH, EE), 256>>>(
        wgu, p_wgu, 2 * II, II, (size_t)HH * 2 * II, (size_t)HH * 2 * II);
    conv_kernel<<<(unsigned)((size_t)EE * II * HH / 4 / 256), 256>>>(wdn, p_wdn, (size_t)EE * II * HH);
    conv_ilv_kernel<<<dim3((2 * SSI) / (4 * 256), HH, 1), 256>>>(
        sgu, p_sgu, 2 * SSI, SSI, 0, 0);
    conv_kernel<<<(unsigned)((size_t)SSI * HH / 4 / 256), 256>>>(sdn, p_sdn, (size_t)SSI * HH);

    // 1. router + compaction
    router_kernel<<<TT / 8, dim3(32, 8)>>>(hs, gw, gb);
    gather_kernel<<<EE, 32>>>();

    // 2. shared gate_up (interleaved N=2*SSI) -> fused silu -> s_hsa hi/lo
    hgemm<false, 1><<<dim3((2 * SSI) / 128, TT / 128, 1), 256, SMEM_BYTES>>>(
        p_hs_h, p_hs_l, 0, HH,
        p_sgu, 0, 2 * SSI,
        nullptr, 0,
        p_hsa_h, p_hsa_l, 0, SSI,
        TT, nullptr, HH, nullptr, nullptr, 0.f);

    // 3. shared down -> out (overwrites poison)
    hgemm<false, 0><<<dim3(HH / 128, TT / 128, 1), 256, SMEM_BYTES>>>(
        p_hsa_h, p_hsa_l, 0, SSI,
        p_sdn, 0, HH,
        out, HH,
        nullptr, nullptr, 0, 0,
        TT, nullptr, SSI, nullptr, nullptr, 0.f);

    // 4. routed gate_up (gather rows, interleaved N=2I) -> fused silu -> g_ha hi/lo
    hgemm<true, 1><<<dim3((2 * II) / 128, TT / 128, EE), 256, SMEM_BYTES>>>(
        p_hs_h, p_hs_l, 0, HH,
        p_wgu, (size_t)HH * 2 * II, 2 * II,
        nullptr, 0,
        p_ha_h, p_ha_l, (size_t)TT * II, II,
        0, p_cnt, HH, p_tok, nullptr, 0.f);

    // 5. routed down + weighted scatter-add -> out
    hgemm<false, 2><<<dim3(HH / 128, TT / 128, EE), 256, SMEM_BYTES>>>(
        p_ha_h, p_ha_l, (size_t)TT * II, II,
        p_wdn, (size_t)II * HH, HH,
        out, HH,
        nullptr, nullptr, 0, 0,
        0, p_cnt, II, p_tok, p_cw, RSCALE);
}

// round 7
// speedup vs baseline: 5.2589x; 1.5563x over previous
#include <cuda_runtime.h>
#include <cuda_fp16.h>
#include <math.h>
#include <stdint.h>

// ---------------- problem constants ----------------
#define TT 4096
#define HH 2048
#define EE 32
#define II 1024
#define TOPK 8
#define NGROUP 8
#define GSIZE 4
#define TOPKG 4
#define SSI 2048
#define RSCALE 2.5f

// ---------------- scratch (device globals) ----------------
__device__ float g_cw[(size_t)TT * EE];
__device__ int   g_tok[(size_t)EE * TT];
__device__ int   g_cnt[EE];

// fp16 operands (all single precision-level: pure fp16 GEMM)
__device__ __half s_hs  [(size_t)TT * HH];
__device__ __half s_wgu [(size_t)EE * HH * 2 * II];   // [e][k=H][n'=2I] gate/up interleaved
__device__ __half s_wdn [(size_t)EE * II * HH];       // [e][k=I][n=H]
__device__ __half s_sgu [(size_t)HH * 2 * SSI];       // [k=H][n'=2SI] interleaved
__device__ __half s_sdn [(size_t)SSI * HH];           // [k=SI][n=H]

// activated intermediates (fp16), row-major [*, I]
__device__ __half g_ha [(size_t)EE * TT * II];
__device__ __half s_hsa[(size_t)TT * SSI];

// ---------------- router ----------------
__global__ void router_kernel(const float* __restrict__ hs,
                              const float* __restrict__ gw,
                              const float* __restrict__ bias) {
    int t    = blockIdx.x * blockDim.y + threadIdx.y;
    int lane = threadIdx.x;
    const float* hrow = hs + (size_t)t * HH;
    float acc = 0.f;
    for (int h = 0; h < HH; h += 4) {
        float4 hv = *(const float4*)(hrow + h);
        acc += hv.x * gw[(h + 0) * EE + lane];
        acc += hv.y * gw[(h + 1) * EE + lane];
        acc += hv.z * gw[(h + 2) * EE + lane];
        acc += hv.w * gw[(h + 3) * EE + lane];
    }
    float score = 1.f / (1.f + expf(-acc));
    float sc    = score + bias[lane];
    __shared__ float s_score[8][32];
    __shared__ float s_sc[8][32];
    s_score[threadIdx.y][lane] = score;
    s_sc[threadIdx.y][lane]    = sc;
    __syncwarp();
    if (lane == 0) {
        float scv[EE], scoresv[EE];
        for (int e = 0; e < EE; e++) { scv[e] = s_sc[threadIdx.y][e]; scoresv[e] = s_score[threadIdx.y][e]; }
        float gs[NGROUP];
        for (int g = 0; g < NGROUP; g++) {
            float m1 = -INFINITY; int i1 = 0;
            for (int j = 0; j < GSIZE; j++) {
                float v = scv[g * GSIZE + j];
                if (v > m1) { m1 = v; i1 = j; }
            }
            float m2 = -INFINITY;
            for (int j = 0; j < GSIZE; j++)
                if (j != i1) { float v = scv[g * GSIZE + j]; if (v > m2) m2 = v; }
            gs[g] = m1 + m2;
        }
        bool gsel[NGROUP];
        for (int g = 0; g < NGROUP; g++) gsel[g] = false;
        for (int it = 0; it < TOPKG; it++) {
            float best = -INFINITY; int bi = 0;
            for (int g = 0; g < NGROUP; g++)
                if (!gsel[g] && gs[g] > best) { best = gs[g]; bi = g; }
            gsel[bi] = true;
        }
        float masked[EE];
        for (int e = 0; e < EE; e++) masked[e] = gsel[e / GSIZE] ? scv[e] : -INFINITY;
        int ids[TOPK]; float wv[TOPK]; float wsum = 0.f;
        for (int k = 0; k < TOPK; k++) {
            float best = -INFINITY; int bi = 0;
            for (int e = 0; e < EE; e++)
                if (masked[e] > best) { best = masked[e]; bi = e; }
            masked[bi] = -INFINITY;
            ids[k] = bi; wv[k] = scoresv[bi]; wsum += wv[k];
        }
        float inv = 1.f / (wsum + 1e-20f);
        float row[EE];
        for (int e = 0; e < EE; e++) row[e] = 0.f;
        for (int k = 0; k < TOPK; k++) row[ids[k]] = wv[k] * inv;
        for (int e = 0; e < EE; e++) g_cw[(size_t)t * EE + e] = row[e];
    }
}

__global__ void gather_kernel() {
    int e = blockIdx.x;
    int lane = threadIdx.x;
    int cnt = 0;
    for (int base = 0; base < TT; base += 32) {
        int t = base + lane;
        bool sel = g_cw[(size_t)t * EE + e] > 0.f;
        unsigned m = __ballot_sync(0xffffffffu, sel);
        int pos = cnt + __popc(m & ((1u << lane) - 1u));
        if (sel) g_tok[(size_t)e * TT + pos] = t;
        cnt += __popc(m);
    }
    if (lane == 0) g_cnt[e] = cnt;
}

// ---------------- fp32 -> fp16 plain convert ----------------
__global__ void conv_kernel(const float* __restrict__ src, __half* __restrict__ dst, size_t n) {
    size_t i = ((size_t)blockIdx.x * blockDim.x + threadIdx.x) * 4;
    if (i >= n) return;
    float4 v = *(const float4*)(src + i);
    __half hv[4] = {__float2half_rn(v.x), __float2half_rn(v.y),
                    __float2half_rn(v.z), __float2half_rn(v.w)};
    *(uint2*)(dst + i) = *(uint2*)hv;
}

// ---------------- fp32 -> fp16 with gate/up column interleave ----------------
__global__ void conv_ilv_kernel(const float* __restrict__ src, __half* __restrict__ dst,
                                int N, int half, size_t sE, size_t dE) {
    int e = blockIdx.z;
    int row = blockIdx.y;
    int n = (blockIdx.x * blockDim.x + threadIdx.x) * 4;
    const float* S = src + (size_t)e * sE + (size_t)row * N;
    __half* D = dst + (size_t)e * dE + (size_t)row * N;
    float4 v = *(const float4*)(S + n);
    float vs[4] = {v.x, v.y, v.z, v.w};
#pragma unroll
    for (int j = 0; j < 4; j++) {
        int nn = n + j;
        int np = (nn < half) ? 2 * nn : 2 * (nn - half) + 1;
        D[np] = __float2half_rn(vs[j]);
    }
}

// ---------------- mma.sync fp16 GEMM ----------------
#define PA 72          // A smem row pitch (elems), BK=64 + 8 pad
#define PB 136         // B smem row pitch (elems), 128 cols + 8 pad
#define BK 64
#define ASZB (128 * PA * 2)        // 18432 bytes per A per stage
#define BSZB (BK * PB * 2)         // 17408 bytes per B per stage
#define STAGE_B (ASZB + BSZB)      // 35840
#define SMEM_BYTES (2 * STAGE_B)   // 71680

__device__ __forceinline__ void cp16(uint32_t dst, const void* src, int sz) {
    asm volatile("cp.async.cg.shared.global [%0], [%1], 16, %2;\n"
                 :: "r"(dst), "l"(src), "r"(sz));
}
__device__ __forceinline__ void cpcommit() { asm volatile("cp.async.commit_group;\n"); }
template<int N> __device__ __forceinline__ void cpwait() {
    asm volatile("cp.async.wait_group %0;\n" :: "n"(N));
}
__device__ __forceinline__ void ldsm4(uint32_t* r, uint32_t addr) {
    asm volatile("ldmatrix.sync.aligned.m8n8.x4.shared.b16 {%0,%1,%2,%3}, [%4];"
                 : "=r"(r[0]), "=r"(r[1]), "=r"(r[2]), "=r"(r[3]) : "r"(addr));
}
__device__ __forceinline__ void ldsm4t(uint32_t* r, uint32_t addr) {
    asm volatile("ldmatrix.sync.aligned.m8n8.x4.trans.shared.b16 {%0,%1,%2,%3}, [%4];"
                 : "=r"(r[0]), "=r"(r[1]), "=r"(r[2]), "=r"(r[3]) : "r"(addr));
}
__device__ __forceinline__ void mmaf16(float* c, const uint32_t* a, uint32_t b0, uint32_t b1) {
    asm volatile("mma.sync.aligned.m16n8k16.row.col.f32.f16.f16.f32 "
                 "{%0,%1,%2,%3}, {%4,%5,%6,%7}, {%8,%9}, {%0,%1,%2,%3};"
                 : "+f"(c[0]), "+f"(c[1]), "+f"(c[2]), "+f"(c[3])
                 : "r"(a[0]), "r"(a[1]), "r"(a[2]), "r"(a[3]), "r"(b0), "r"(b1));
}

// GA: gather A rows by token list.
// EPI: 0 plain fp32 store; 1 silu(gate)*up -> fp16 (interleaved cols); 2 weighted atomicAdd scatter
template<bool GA, int EPI>
__global__ __launch_bounds__(256, 2)
void hgemm(const __half* __restrict__ A, size_t sAe, int lda,
           const __half* __restrict__ B, size_t sBe, int ldb,
           float* __restrict__ C, int ldc,
           __half* __restrict__ D, size_t sDe, int ldd,
           int Mdir, const int* __restrict__ cntp, int K,
           const int* __restrict__ tokall,
           const float* __restrict__ cw, float wscale)
{
    extern __shared__ char smraw[];
    int z = blockIdx.z;
    int M = cntp ? cntp[z] : Mdir;
    int row0 = blockIdx.y * 128;
    if (row0 >= M) return;
    int col0 = blockIdx.x * 128;

    const __half* Az = A + (size_t)z * sAe;
    const __half* Bz = B + (size_t)z * sBe;
    const int* tokz = (GA || EPI == 2) ? tokall + (size_t)z * TT : nullptr;

    int tid = threadIdx.x;
    uint32_t sb = (uint32_t)__cvta_generic_to_shared(smraw);

    // A rows: rows (tid>>3)+32*it, seg (tid&7)*8 elems
    long aRow[4];
    int r0t = tid >> 3;
    int seg = (tid & 7) * 8;
#pragma unroll
    for (int it = 0; it < 4; it++) {
        int grow = row0 + r0t + 32 * it;
        if (grow < M) aRow[it] = GA ? (long)tokz[grow] : (long)grow;
        else          aRow[it] = -1;
    }

    auto load_stage = [&](int kt, int s) {
        uint32_t base = sb + (uint32_t)s * STAGE_B;
#pragma unroll
        for (int it = 0; it < 4; it++) {
            int r = r0t + 32 * it;
            uint32_t d = base + (uint32_t)(r * PA + seg) * 2;
            long src = aRow[it];
            const __half* pa = (src >= 0) ? Az + (size_t)src * lda + kt * BK + seg : Az;
            cp16(d, pa, (src >= 0) ? 16 : 0);
        }
#pragma unroll
        for (int it = 0; it < 4; it++) {
            int q = tid + it * 256;
            int kr = q >> 4;
            int ns = (q & 15) * 8;
            uint32_t d = base + ASZB + (uint32_t)(kr * PB + ns) * 2;
            cp16(d, Bz + (size_t)(kt * BK + kr) * ldb + col0 + ns, 16);
        }
        cpcommit();
    };

    int lane = tid & 31, wid = tid >> 5;
    int wm = wid & 3, wn = wid >> 2;   // 4 warps M (32 rows), 2 warps N (64 cols)

    float acc[2][8][4];
#pragma unroll
    for (int a = 0; a < 2; a++)
#pragma unroll
        for (int b = 0; b < 8; b++)
#pragma unroll
            for (int c = 0; c < 4; c++) acc[a][b][c] = 0.f;

    int NT = K / BK;
    load_stage(0, 0);
    for (int kt = 0; kt < NT; kt++) {
        int s = kt & 1;
        if (kt + 1 < NT) { load_stage(kt + 1, (kt + 1) & 1); cpwait<1>(); }
        else             { cpwait<0>(); }
        __syncthreads();
        uint32_t base = sb + (uint32_t)s * STAGE_B;
        int arow = lane & 15;
        int achk = lane >> 4;
#pragma unroll
        for (int s2 = 0; s2 < 4; s2++) {
            int k0 = s2 * 16;
            uint32_t a_r[2][4];
#pragma unroll
            for (int mt = 0; mt < 2; mt++) {
                uint32_t off = (uint32_t)((wm * 32 + mt * 16 + arow) * PA + k0 + achk * 8) * 2;
                ldsm4(a_r[mt], base + off);
            }
#pragma unroll
            for (int nt = 0; nt < 4; nt++) {
                uint32_t boff = (uint32_t)((k0 + arow) * PB + wn * 64 + nt * 16 + achk * 8) * 2;
                uint32_t bfr[4];
                ldsm4t(bfr, base + ASZB + boff);
#pragma unroll
                for (int mt = 0; mt < 2; mt++) {
#pragma unroll
                    for (int j = 0; j < 2; j++)
                        mmaf16(acc[mt][nt * 2 + j], a_r[mt], bfr[2 * j], bfr[2 * j + 1]);
                }
            }
        }
        __syncthreads();
    }

    // ---------------- epilogue ----------------
    int r_base = row0 + wm * 32 + (lane >> 2);
    int c_base = col0 + wn * 64 + (lane & 3) * 2;
#pragma unroll
    for (int mt = 0; mt < 2; mt++) {
#pragma unroll
        for (int half = 0; half < 2; half++) {
            int r = r_base + mt * 16 + half * 8;
            if (r >= M) continue;
            if (EPI == 0) {
                float* Crow = C + (size_t)r * ldc;
#pragma unroll
                for (int q = 0; q < 8; q++) {
                    int c = c_base + q * 8;
                    float2 v = make_float2(acc[mt][q][half * 2 + 0], acc[mt][q][half * 2 + 1]);
                    *(float2*)&Crow[c] = v;
                }
            } else if (EPI == 1) {
                // even col = gate, odd col = up (interleaved weight cols)
                int cb2 = (c_base >> 1);
                __half* DR = D + (size_t)z * sDe + (size_t)r * ldd;
#pragma unroll
                for (int q = 0; q < 8; q++) {
                    float g = acc[mt][q][half * 2 + 0];
                    float u = acc[mt][q][half * 2 + 1];
                    float h = u * (g / (1.f + expf(-g)));
                    DR[cb2 + q * 4] = __float2half_rn(h);
                }
            } else {  // EPI == 2
                int t = tokz[r];
                float wt = wscale * cw[(size_t)t * EE + z];
                float* Crow = C + (size_t)t * ldc;
#pragma unroll
                for (int q = 0; q < 8; q++) {
                    int c = c_base + q * 8;
                    atomicAdd(&Crow[c],     wt * acc[mt][q][half * 2 + 0]);
                    atomicAdd(&Crow[c + 1], wt * acc[mt][q][half * 2 + 1]);
                }
            }
        }
    }
}

// ---------------- launcher ----------------
extern "C" void kernel_launch(void* const* d_in, const int* in_sizes, int n_in,
                              void* d_out, int out_size) {
    const float* hs  = (const float*)d_in[0];
    const float* gw  = (const float*)d_in[1];
    const float* gb  = (const float*)d_in[2];
    const float* wgu = (const float*)d_in[3];  // [E,H,2I]
    const float* wdn = (const float*)d_in[4];  // [E,I,H]
    const float* sgu = (const float*)d_in[5];  // [H,2SI]
    const float* sdn = (const float*)d_in[6];  // [SI,H]
    float* out = (float*)d_out;

    cudaFuncSetAttribute((const void*)hgemm<false, 0>, cudaFuncAttributeMaxDynamicSharedMemorySize, SMEM_BYTES);
    cudaFuncSetAttribute((const void*)hgemm<false, 1>, cudaFuncAttributeMaxDynamicSharedMemorySize, SMEM_BYTES);
    cudaFuncSetAttribute((const void*)hgemm<true,  1>, cudaFuncAttributeMaxDynamicSharedMemorySize, SMEM_BYTES);
    cudaFuncSetAttribute((const void*)hgemm<false, 2>, cudaFuncAttributeMaxDynamicSharedMemorySize, SMEM_BYTES);

    __half *p_hs, *p_wgu, *p_wdn, *p_sgu, *p_sdn, *p_ha, *p_hsa;
    float *p_cw;
    int *p_tok, *p_cnt;
    cudaGetSymbolAddress((void**)&p_hs,  s_hs);
    cudaGetSymbolAddress((void**)&p_wgu, s_wgu);
    cudaGetSymbolAddress((void**)&p_wdn, s_wdn);
    cudaGetSymbolAddress((void**)&p_sgu, s_sgu);
    cudaGetSymbolAddress((void**)&p_sdn, s_sdn);
    cudaGetSymbolAddress((void**)&p_ha,  g_ha);
    cudaGetSymbolAddress((void**)&p_hsa, s_hsa);
    cudaGetSymbolAddress((void**)&p_cw,  g_cw);
    cudaGetSymbolAddress((void**)&p_tok, g_tok);
    cudaGetSymbolAddress((void**)&p_cnt, g_cnt);

    // 0. conversions
    conv_kernel<<<(unsigned)((size_t)TT * HH / 4 / 256), 256>>>(hs, p_hs, (size_t)TT * HH);
    conv_ilv_kernel<<<dim3((2 * II) / (4 * 256), HH, EE), 256>>>(
        wgu, p_wgu, 2 * II, II, (size_t)HH * 2 * II, (size_t)HH * 2 * II);
    conv_kernel<<<(unsigned)((size_t)EE * II * HH / 4 / 256), 256>>>(wdn, p_wdn, (size_t)EE * II * HH);
    conv_ilv_kernel<<<dim3((2 * SSI) / (4 * 256), HH, 1), 256>>>(
        sgu, p_sgu, 2 * SSI, SSI, 0, 0);
    conv_kernel<<<(unsigned)((size_t)SSI * HH / 4 / 256), 256>>>(sdn, p_sdn, (size_t)SSI * HH);

    // 1. router + compaction
    router_kernel<<<TT / 8, dim3(32, 8)>>>(hs, gw, gb);
    gather_kernel<<<EE, 32>>>();

    // 2. shared gate_up (interleaved N=2*SSI) -> fused silu -> s_hsa
    hgemm<false, 1><<<dim3((2 * SSI) / 128, TT / 128, 1), 256, SMEM_BYTES>>>(
        p_hs, 0, HH,
        p_sgu, 0, 2 * SSI,
        nullptr, 0,
        p_hsa, 0, SSI,
        TT, nullptr, HH, nullptr, nullptr, 0.f);

    // 3. shared down -> out (overwrites poison)
    hgemm<false, 0><<<dim3(HH / 128, TT / 128, 1), 256, SMEM_BYTES>>>(
        p_hsa, 0, SSI,
        p_sdn, 0, HH,
        out, HH,
        nullptr, 0, 0,
        TT, nullptr, SSI, nullptr, nullptr, 0.f);

    // 4. routed gate_up (gather rows, interleaved N=2I) -> fused silu -> g_ha
    hgemm<true, 1><<<dim3((2 * II) / 128, TT / 128, EE), 256, SMEM_BYTES>>>(
        p_hs, 0, HH,
        p_wgu, (size_t)HH * 2 * II, 2 * II,
        nullptr, 0,
        p_ha, (size_t)TT * II, II,
        0, p_cnt, HH, p_tok, nullptr, 0.f);

    // 5. routed down + weighted scatter-add -> out
    hgemm<false, 2><<<dim3(HH / 128, TT / 128, EE), 256, SMEM_BYTES>>>(
        p_ha, (size_t)TT * II, II,
        p_wdn, (size_t)II * HH, HH,
        out, HH,
        nullptr, 0, 0,
        0, p_cnt, II, p_tok, p_cw, RSCALE);
}